// round 17
// baseline (speedup 1.0000x reference)
#include <cuda_runtime.h>

// RandomShiftsAug on GB300 — integer-shift copy with edge clamp.
// out[n,c,y,x] = in[n,c, clamp(y+sy-4,0,127), clamp(x+sx-4,0,127)]
//
// FINAL (R13): register+shuffle shift, zero smem, zero barriers, MLP=4.
//  Warp owns 4 rows of one (n,c) image. Lane l holds aligned quad l of its
//  row (1 LDG.128, .cs + L2::256B hint). Output quad cols 4l+sx..+3 are
//  consecutive, so each output word is one shfl of a WARP-UNIFORM component
//  ((sx+j)&3) from lane (4l+sx+j)>>2. Edge clamp via warp-uniform-guarded
//  shfl of col 0 / col 127 + predicated selects (only lanes 0/31 trigger).
//  Per 512B row: 4 LDG.128 + 4 STG.128 wavefronts — pure-copy L1 cost.
//
//  Measured: 90.18 us wall, DRAM 81-82% (6.4-6.5 TB/s). Five structurally
//  different schedules plateau here -> HBM mixed-R/W roofline for 604 MB.

#define PADV 4
#define CB   9
#define HB   128
#define RW   4
#define FULLM 0xFFFFFFFFu

__device__ __forceinline__ float4 ldcs_256(const float4* p)
{
    float4 v;
    asm volatile("ld.global.cs.L2::256B.v4.f32 {%0,%1,%2,%3}, [%4];"
                 : "=f"(v.x), "=f"(v.y), "=f"(v.z), "=f"(v.w)
                 : "l"(p));
    return v;
}

__global__ void __launch_bounds__(256)
random_shift_shfl2_kernel(const float* __restrict__ x,
                          const int* __restrict__ shift,
                          float* __restrict__ out)
{
    int w = threadIdx.x >> 5;
    int l = threadIdx.x & 31;

    int gwarp = blockIdx.x * 8 + w;    // 147456 warps
    int grp   = gwarp & 31;            // 32 row-quartets per image
    int nc    = gwarp >> 5;            // n*9 + c
    int y0    = grp << 2;
    int n     = nc / CB;

    int sx = shift[2 * n]     - PADV;  // warp-uniform, in [-4,4]
    int sy = shift[2 * n + 1] - PADV;

    const float4* __restrict__ img4 =
        reinterpret_cast<const float4*>(x) + nc * (HB * HB / 4);

    // ---- 4 aligned LDG.128 in flight ----
    float4 A[RW];
    #pragma unroll
    for (int r = 0; r < RW; r++) {
        int ys = y0 + r + sy;
        ys = ys < 0 ? 0 : (ys > HB - 1 ? HB - 1 : ys);
        A[r] = ldcs_256(img4 + ys * (HB / 4) + l);
    }

    int c0 = (l << 2) + sx;            // first source col of my output quad
    int q0 = c0 >> 2;                  // arithmetic shift = floor divide
    int qa = q0 < 0 ? 0 : (q0 > 31 ? 31 : q0);
    int qb = q0 + 1 > 31 ? 31 : q0 + 1;
    int rot = sx & 3;                  // warp-uniform

    float4* __restrict__ dst4 =
        reinterpret_cast<float4*>(out) + (nc * HB + y0) * (HB / 4) + l;

    #pragma unroll
    for (int r = 0; r < RW; r++) {
        float4 a = A[r];
        float o0, o1, o2, o3;
        switch (rot) {                 // warp-uniform branch
        case 0:
            o0 = __shfl_sync(FULLM, a.x, qa); o1 = __shfl_sync(FULLM, a.y, qa);
            o2 = __shfl_sync(FULLM, a.z, qa); o3 = __shfl_sync(FULLM, a.w, qa);
            break;
        case 1:
            o0 = __shfl_sync(FULLM, a.y, qa); o1 = __shfl_sync(FULLM, a.z, qa);
            o2 = __shfl_sync(FULLM, a.w, qa); o3 = __shfl_sync(FULLM, a.x, qb);
            break;
        case 2:
            o0 = __shfl_sync(FULLM, a.z, qa); o1 = __shfl_sync(FULLM, a.w, qa);
            o2 = __shfl_sync(FULLM, a.x, qb); o3 = __shfl_sync(FULLM, a.y, qb);
            break;
        default:
            o0 = __shfl_sync(FULLM, a.w, qa); o1 = __shfl_sync(FULLM, a.x, qb);
            o2 = __shfl_sync(FULLM, a.y, qb); o3 = __shfl_sync(FULLM, a.z, qb);
            break;
        }

        // Edge clamp — warp-uniform guarded (shfls are warp-wide inside).
        if (sx < 0) {                  // only left edge (lane 0) can clamp low
            float first = __shfl_sync(FULLM, a.x, 0);    // col 0
            if (c0     < 0) o0 = first;
            if (c0 + 1 < 0) o1 = first;
            if (c0 + 2 < 0) o2 = first;
            if (c0 + 3 < 0) o3 = first;
        } else if (sx > 0) {           // only right edge (lane 31) can clamp high
            float last = __shfl_sync(FULLM, a.w, 31);    // col 127
            if (c0     > HB - 1) o0 = last;
            if (c0 + 1 > HB - 1) o1 = last;
            if (c0 + 2 > HB - 1) o2 = last;
            if (c0 + 3 > HB - 1) o3 = last;
        }

        float4 v; v.x = o0; v.y = o1; v.z = o2; v.w = o3;
        __stcs(dst4 + r * (HB / 4), v);
    }
}

extern "C" void kernel_launch(void* const* d_in, const int* in_sizes, int n_in,
                              void* d_out, int out_size)
{
    const float* x     = (const float*)d_in[0];
    const int*   shift = (const int*)d_in[1];
    float*       out   = (float*)d_out;

    // 4608 images * 32 row-quartets = 147456 warps / 8 per CTA = 18432 CTAs
    random_shift_shfl2_kernel<<<18432, 256>>>(x, shift, out);
}